// round 10
// baseline (speedup 1.0000x reference)
#include <cuda_runtime.h>
#include <cuda_bf16.h>

#define O_     4
#define N_     3072
#define KNN    10
#define TOLC   0.01f
#define FMAXV  3.402823466e+38f
#define BTHR   128           // threads per knn block (1 query/thread)
#define CAP    160           // per-thread commit buffer (mean ~75, >10 sigma)
#define NSTRIP 24
#define SLEN   128           // candidates per strip
#define NS     4096          // bitonic pad
#define FULLM  0xFFFFFFFFu

// ---------------- device scratch (no allocations allowed) ----------------
__device__ float4 g_pip4[O_ * N_];     // (x, y, z, |p|^2), original order
__device__ float4 g_nrm4[O_ * N_];     // raw normal, original order
__device__ float4 g_spip[O_][N_];      // x-sorted positions
__device__ float4 g_snrm[O_][N_];      // x-sorted normals
__device__ int    g_sid [O_][N_];      // sorted rank -> original index
__device__ float  g_scr[O_][3][N_];    // signed nearest distance (original index)

__device__ __forceinline__ unsigned f2ord(float f) {
    unsigned b = __float_as_uint(f);
    return b ^ ((unsigned)(((int)b) >> 31) | 0x80000000u);
}

// ---------------- kernel 1: prep + transform fused ----------------
__global__ void transform_kernel(const float* __restrict__ points,
                                 const float* __restrict__ T_obj,
                                 const float* __restrict__ T_plane) {
    int i = blockIdx.x * blockDim.x + threadIdx.x;
    if (i >= O_ * N_) return;
    int o = i / N_;

    float Rp[9], tp[3];
    #pragma unroll
    for (int r = 0; r < 3; r++) {
        #pragma unroll
        for (int c = 0; c < 3; c++) Rp[r * 3 + c] = __ldg(&T_plane[r * 4 + c]);
        tp[r] = __ldg(&T_plane[r * 4 + 3]);
    }
    const float* To = T_obj + o * 16;
    float R[3][3], tr[3];
    #pragma unroll
    for (int r = 0; r < 3; r++) {
        R[r][0] = Rp[0 + r] * To[0] + Rp[3 + r] * To[4] + Rp[6 + r] * To[8];
        R[r][1] = Rp[0 + r] * To[1] + Rp[3 + r] * To[5] + Rp[6 + r] * To[9];
        R[r][2] = Rp[0 + r] * To[2] + Rp[3 + r] * To[6] + Rp[6 + r] * To[10];
        tr[r]   = Rp[0 + r] * (To[3] - tp[0]) + Rp[3 + r] * (To[7] - tp[1])
                + Rp[6 + r] * (To[11] - tp[2]);
    }

    const float* p = points + (size_t)i * 6;
    float x = p[0], y = p[1], z = p[2];
    float px = fmaf(R[0][0], x, fmaf(R[0][1], y, fmaf(R[0][2], z, tr[0])));
    float py = fmaf(R[1][0], x, fmaf(R[1][1], y, fmaf(R[1][2], z, tr[1])));
    float pz = fmaf(R[2][0], x, fmaf(R[2][1], y, fmaf(R[2][2], z, tr[2])));
    float rr = px * px + py * py + pz * pz;
    g_pip4[i] = make_float4(px, py, pz, rr);
    g_nrm4[i] = make_float4(p[3], p[4], p[5], 0.f);
}

// ---------------- kernel 1b: exact x-sort per object (bitonic on u64 keys) ----------------
__global__ void __launch_bounds__(1024) sortx_kernel() {
    __shared__ unsigned long long sk[NS];
    int o = blockIdx.x;
    for (int i = threadIdx.x; i < NS; i += 1024) {
        unsigned long long key = 0xFFFFFFFFFFFFFFFFull;
        if (i < N_)
            key = ((unsigned long long)f2ord(g_pip4[o * N_ + i].x) << 12) | (unsigned)i;
        sk[i] = key;
    }
    __syncthreads();
    for (int k = 2; k <= NS; k <<= 1) {
        for (int j = k >> 1; j > 0; j >>= 1) {
            for (int i = threadIdx.x; i < NS; i += 1024) {
                int ixj = i ^ j;
                if (ixj > i) {
                    unsigned long long a = sk[i], b = sk[ixj];
                    bool up = ((i & k) == 0);
                    if ((a > b) == up) { sk[i] = b; sk[ixj] = a; }
                }
            }
            __syncthreads();
        }
    }
    for (int r = threadIdx.x; r < N_; r += 1024) {
        int idx = (int)(sk[r] & 0xFFFu);
        g_spip[o][r] = g_pip4[o * N_ + idx];
        g_snrm[o][r] = g_nrm4[o * N_ + idx];
        g_sid [o][r] = idx;
    }
}

// ---------------- kernel 2: strip-pruned exact top-10 per (b, o!=b, query) ----------------
__global__ void __launch_bounds__(BTHR) knn_kernel() {
    extern __shared__ float4 sh[];                       // N_ sorted candidates
    __shared__ float sxmin[NSTRIP], sxmax[NSTRIP];
    unsigned short* buf = (unsigned short*)(sh + N_);    // buf[slot*BTHR + tid]

    int pair = blockIdx.y;
    int b  = pair / 3;
    int oi = pair - b * 3;
    int o  = oi + (oi >= b ? 1 : 0);
    int tid = threadIdx.x;
    int qrank = blockIdx.x * BTHR + tid;                 // sorted query rank in object b

    const float4* cand = &g_spip[o][0];
    for (int i = tid; i < N_; i += BTHR) sh[i] = cand[i];
    __syncthreads();
    if (tid < NSTRIP) {
        sxmin[tid] = sh[tid * SLEN].x;
        sxmax[tid] = sh[tid * SLEN + SLEN - 1].x;
    }
    __syncthreads();

    float4 q = g_spip[b][qrank];
    int orig_n = g_sid[b][qrank];
    float m2x = -2.f * q.x, m2y = -2.f * q.y, m2z = -2.f * q.z;

    float a[KNN];
    #pragma unroll
    for (int s = 0; s < KNN; s++) a[s] = FMAXV;
    float thresh = FMAXV;
    int cnt = 0, start = 0;

    // chain insert (branchy, used by seed & replay)
    #define CHAIN_INSERT(dv)                              \
        do { float _t = (dv);                             \
             _Pragma("unroll")                            \
             for (int _s = 0; _s < KNN; _s++) {           \
                 float _lo = fminf(a[_s], _t);            \
                 _t = fmaxf(a[_s], _t);                   \
                 a[_s] = _lo;                             \
             }                                            \
             thresh = a[KNN - 1]; } while (0)

    #define REPLAY()                                                          \
        do { int _stop = cnt < CAP ? cnt : CAP;                               \
             _Pragma("unroll 1")                                              \
             for (int _t = start; ; _t++) {                                   \
                 bool _act = _t < _stop;                                      \
                 if (!__any_sync(FULLM, _act)) break;                         \
                 if (_act) {                                                  \
                     unsigned _id = buf[_t * BTHR + tid];                     \
                     float4 _c = sh[_id];                                     \
                     float _d = fmaf(_c.x, m2x,                               \
                                fmaf(_c.y, m2y, fmaf(_c.z, m2z, _c.w)));      \
                     if (_d < thresh) CHAIN_INSERT(_d);                       \
                 }                                                            \
             }                                                                \
             start = _stop; } while (0)

    // branchless scan of one strip, then replay
    #define SCAN_STRIP(sidx)                                                  \
        do { int _base = (sidx) * SLEN;                                       \
             _Pragma("unroll 1")                                              \
             for (int _jj = 0; _jj < SLEN; _jj += 8) {                        \
                 float _d[8];                                                 \
                 _Pragma("unroll")                                            \
                 for (int _u = 0; _u < 8; _u++) {                             \
                     float4 _c = sh[_base + _jj + _u];                        \
                     _d[_u] = fmaf(_c.x, m2x,                                 \
                               fmaf(_c.y, m2y, fmaf(_c.z, m2z, _c.w)));       \
                 }                                                            \
                 _Pragma("unroll")                                            \
                 for (int _u = 0; _u < 8; _u++) {                             \
                     int _slot = cnt < CAP - 1 ? cnt : CAP - 1;               \
                     buf[_slot * BTHR + tid] =                                \
                         (unsigned short)(_base + _jj + _u);                  \
                     cnt += (_d[_u] < thresh) ? 1 : 0;                        \
                 }                                                            \
             }                                                                \
             REPLAY(); } while (0)

    // home strip (warp-uniform; queries are x-sorted so lanes agree +/-1)
    int s0 = 0;
    #pragma unroll 1
    for (int s = 1; s < NSTRIP; s++) if (q.x >= sxmin[s]) s0 = s;
    int sw = __shfl_sync(FULLM, s0, 0);

    // seed: first 32 of home strip with branchy chain (bounds commit count)
    {
        int base = sw * SLEN;
        #pragma unroll 1
        for (int j = 0; j < 32; j++) {
            float4 c = sh[base + j];
            float d = fmaf(c.x, m2x, fmaf(c.y, m2y, fmaf(c.z, m2z, c.w)));
            if (d < thresh) {
                int slot = cnt < CAP - 1 ? cnt : CAP - 1;
                buf[slot * BTHR + tid] = (unsigned short)(base + j);
                cnt++;
                CHAIN_INSERT(d);
            }
        }
        start = cnt < CAP ? cnt : CAP;
        // rest of home strip, branchless
        #pragma unroll 1
        for (int jj = 32; jj < SLEN; jj += 8) {
            float d[8];
            #pragma unroll
            for (int u = 0; u < 8; u++) {
                float4 c = sh[base + jj + u];
                d[u] = fmaf(c.x, m2x, fmaf(c.y, m2y, fmaf(c.z, m2z, c.w)));
            }
            #pragma unroll
            for (int u = 0; u < 8; u++) {
                int slot = cnt < CAP - 1 ? cnt : CAP - 1;
                buf[slot * BTHR + tid] = (unsigned short)(base + jj + u);
                cnt += (d[u] < thresh) ? 1 : 0;
            }
        }
        REPLAY();
    }

    // expand outward with exact pruning: D >= (gap_x)^2, bound = q.w + a[9]
    {
        int up = sw + 1, dn = sw - 1;
        #pragma unroll 1
        while (up < NSTRIP || dn >= 0) {
            if (up < NSTRIP) {
                float gap = fmaxf(0.f, sxmin[up] - q.x);
                bool need = gap * gap <= q.w + thresh;
                if (__any_sync(FULLM, need)) { SCAN_STRIP(up); up++; }
                else up = NSTRIP;
            }
            if (dn >= 0) {
                float gap = fmaxf(0.f, q.x - sxmax[dn]);
                bool need = gap * gap <= q.w + thresh;
                if (__any_sync(FULLM, need)) { SCAN_STRIP(dn); dn--; }
                else dn = -1;
            }
        }
    }

    // ---- final id selection (ranks into sorted arrays) ----
    unsigned ids[KNN];
    int w = 0;
    if (cnt < CAP) {
        #pragma unroll 1
        for (int t = 0; t < cnt && w < KNN; t++) {
            unsigned id = buf[t * BTHR + tid];
            float4 c = sh[id];
            float d = fmaf(c.x, m2x, fmaf(c.y, m2y, fmaf(c.z, m2z, c.w)));
            if (d <= thresh) ids[w++] = id;
        }
    } else {
        // overflow fallback: exact full redo over all candidates
        #pragma unroll
        for (int s = 0; s < KNN; s++) a[s] = FMAXV;
        thresh = FMAXV;
        #pragma unroll 1
        for (int j = 0; j < N_; j++) {
            float4 c = sh[j];
            float d = fmaf(c.x, m2x, fmaf(c.y, m2y, fmaf(c.z, m2z, c.w)));
            if (d < thresh) CHAIN_INSERT(d);
        }
        #pragma unroll 1
        for (int j = 0; j < N_ && w < KNN; j++) {
            float4 c = sh[j];
            float d = fmaf(c.x, m2x, fmaf(c.y, m2y, fmaf(c.z, m2z, c.w)));
            if (d <= thresh) ids[w++] = (unsigned)j;
        }
    }
    while (w < KNN) ids[w++] = ids[0];   // safety (unreachable)

    // ---- exact d0 + inside votes ----
    float D = q.w + a[0];
    float d0 = sqrtf(fmaxf(D, 0.f));

    int votes = 0;
    const float4* nrm = &g_snrm[o][0];
    #pragma unroll
    for (int s = 0; s < KNN; s++) {
        unsigned id = ids[s];
        float4 c  = sh[id];
        float4 nm = __ldg(&nrm[id]);
        float dt = (c.x - q.x) * nm.x + (c.y - q.y) * nm.y + (c.z - q.z) * nm.z;
        votes += (dt > 0.f) ? 1 : 0;
    }
    float sd = (votes > 8) ? -d0 : d0;   // sum(insides) > 0.8*k -> >= 9
    g_scr[b][oi][orig_n] = sd;

    #undef SCAN_STRIP
    #undef REPLAY
    #undef CHAIN_INSERT
}

// ---------------- kernel 3: min over other objects + plane, write out ----------------
__global__ void finalize_kernel(float* __restrict__ out, int out_size) {
    int i = blockIdx.x * blockDim.x + threadIdx.x;
    if (i >= O_ * N_) return;
    int b = i / N_;
    int n = i % N_;
    float sd = g_pip4[i].z;                 // plane signed distance = pip.z
    sd = fminf(sd, g_scr[b][0][n]);
    sd = fminf(sd, g_scr[b][1][n]);
    sd = fminf(sd, g_scr[b][2][n]);
    out[i] = sd;
    if (out_size >= 2 * O_ * N_)
        out[O_ * N_ + i] = (sd < -TOLC) ? 1.0f : 0.0f;
}

// ---------------- launch ----------------
extern "C" void kernel_launch(void* const* d_in, const int* in_sizes, int n_in,
                              void* d_out, int out_size) {
    const float* points  = nullptr;
    const float* T_obj   = nullptr;
    const float* T_plane = nullptr;
    for (int i = 0; i < n_in; i++) {
        if (in_sizes[i] == O_ * N_ * 6) points  = (const float*)d_in[i];
        else if (in_sizes[i] == 64)     T_obj   = (const float*)d_in[i];
        else if (in_sizes[i] == 16)     T_plane = (const float*)d_in[i];
    }

    transform_kernel<<<(O_ * N_ + 255) / 256, 256>>>(points, T_obj, T_plane);
    sortx_kernel<<<O_, 1024>>>();

    int smem = N_ * (int)sizeof(float4) + CAP * BTHR * (int)sizeof(unsigned short);
    (void)cudaFuncSetAttribute(knn_kernel,
                               cudaFuncAttributeMaxDynamicSharedMemorySize, smem);
    knn_kernel<<<dim3(N_ / BTHR, O_ * 3), BTHR, smem>>>();

    finalize_kernel<<<(O_ * N_ + 255) / 256, 256>>>((float*)d_out, out_size);
}

// round 12
// speedup vs baseline: 1.4537x; 1.4537x over previous
#include <cuda_runtime.h>
#include <cuda_bf16.h>

#define O_    4
#define N_    3072
#define KNN   10
#define TOLC  0.01f
#define FMAXV 3.402823466e+38f
#define BTHR  128            // threads per knn block (1 query/thread)
#define CAP   112            // per-thread insert buffer (mean ~57, ~7 sigma)
#define FULLM 0xFFFFFFFFu

// ---------------- device scratch (no allocations allowed) ----------------
__device__ float4 g_pip4[O_ * N_];     // (x, y, z, |p|^2)
__device__ float4 g_nrm4[O_ * N_];     // raw normal
__device__ float  g_scr[O_][3][N_];    // signed nearest distance per (b, other-idx, n)

// ---------------- kernel 1: prep + transform fused ----------------
__global__ void transform_kernel(const float* __restrict__ points,
                                 const float* __restrict__ T_obj,
                                 const float* __restrict__ T_plane) {
    int i = blockIdx.x * blockDim.x + threadIdx.x;
    if (i >= O_ * N_) return;
    int o = i / N_;

    float Rp[9], tp[3];
    #pragma unroll
    for (int r = 0; r < 3; r++) {
        #pragma unroll
        for (int c = 0; c < 3; c++) Rp[r * 3 + c] = __ldg(&T_plane[r * 4 + c]);
        tp[r] = __ldg(&T_plane[r * 4 + 3]);
    }
    const float* To = T_obj + o * 16;
    // inv(T_plane) rigid: [Rp^T | -Rp^T tp]
    float R[3][3], tr[3];
    #pragma unroll
    for (int r = 0; r < 3; r++) {
        R[r][0] = Rp[0 + r] * To[0] + Rp[3 + r] * To[4] + Rp[6 + r] * To[8];
        R[r][1] = Rp[0 + r] * To[1] + Rp[3 + r] * To[5] + Rp[6 + r] * To[9];
        R[r][2] = Rp[0 + r] * To[2] + Rp[3 + r] * To[6] + Rp[6 + r] * To[10];
        tr[r]   = Rp[0 + r] * (To[3] - tp[0]) + Rp[3 + r] * (To[7] - tp[1])
                + Rp[6 + r] * (To[11] - tp[2]);
    }

    const float* p = points + (size_t)i * 6;
    float x = p[0], y = p[1], z = p[2];
    float px = fmaf(R[0][0], x, fmaf(R[0][1], y, fmaf(R[0][2], z, tr[0])));
    float py = fmaf(R[1][0], x, fmaf(R[1][1], y, fmaf(R[1][2], z, tr[1])));
    float pz = fmaf(R[2][0], x, fmaf(R[2][1], y, fmaf(R[2][2], z, tr[2])));
    float rr = px * px + py * py + pz * pz;
    g_pip4[i] = make_float4(px, py, pz, rr);
    g_nrm4[i] = make_float4(p[3], p[4], p[5], 0.f);
}

// ---------------- kernel 2: exact top-10 per (b, o!=b, n) — bitmask collect + replay ----------------
// smem: [0,48K) candidates float4 ; [48K,+28K) insert-id buffer u16 [CAP][BTHR]
__global__ void __launch_bounds__(BTHR) knn_kernel() {
    extern __shared__ float4 sh[];
    unsigned short* buf = (unsigned short*)(sh + N_);   // buf[slot*BTHR + tid]
    int pair = blockIdx.y;
    int b  = pair / 3;
    int oi = pair - b * 3;
    int o  = oi + (oi >= b ? 1 : 0);
    int tid = threadIdx.x;
    int n  = blockIdx.x * BTHR + tid;

    const float4* cand = g_pip4 + o * N_;
    for (int i = tid; i < N_; i += BTHR) sh[i] = cand[i];
    __syncthreads();

    float4 q = g_pip4[b * N_ + n];
    float m2x = -2.f * q.x, m2y = -2.f * q.y, m2z = -2.f * q.z;

    float a[KNN];
    #pragma unroll
    for (int s = 0; s < KNN; s++) a[s] = FMAXV;
    float thresh = FMAXV;
    int cnt = 0;

    // ---- scan: 32-candidate chunks; branchless mask build, then replay set bits ----
    #pragma unroll 1
    for (int j0 = 0; j0 < N_; j0 += 32) {
        unsigned mask = 0u;
        #pragma unroll
        for (int u = 0; u < 32; u++) {
            float4 c = sh[j0 + u];      // warp-uniform address -> broadcast, conflict-free
            float d = fmaf(c.x, m2x, fmaf(c.y, m2y, fmaf(c.z, m2z, c.w)));
            mask |= (d < thresh) ? (1u << u) : 0u;
        }
        #pragma unroll 1
        while (__any_sync(FULLM, mask != 0u)) {
            if (mask) {
                int bit = __ffs(mask) - 1;
                mask &= mask - 1u;
                int id = j0 + bit;
                float4 c = sh[id];
                float d = fmaf(c.x, m2x, fmaf(c.y, m2y, fmaf(c.z, m2z, c.w)));
                if (d < thresh) {       // recheck against refined threshold
                    int slot = cnt < CAP - 1 ? cnt : CAP - 1;
                    buf[slot * BTHR + tid] = (unsigned short)id;
                    cnt++;
                    float t = d;
                    #pragma unroll
                    for (int s = 0; s < KNN; s++) {
                        float lo = fminf(a[s], t);
                        t = fmaxf(a[s], t);
                        a[s] = lo;
                    }
                    thresh = a[KNN - 1];
                }
            }
        }
    }
    // a[0..9] is now the EXACT top-10 (every candidate below the running
    // threshold was replayed; threshold only decreases -> superset argument).

    // ---- final id selection: first 10 buffered ids (ascending j) with d <= a[9] ----
    unsigned ids[KNN];
    int w = 0;
    if (cnt < CAP) {
        #pragma unroll 1
        for (int t = 0; t < cnt && w < KNN; t++) {
            unsigned id = buf[t * BTHR + tid];
            float4 c = sh[id];
            float d = fmaf(c.x, m2x, fmaf(c.y, m2y, fmaf(c.z, m2z, c.w)));
            if (d <= thresh) ids[w++] = id;
        }
    } else {
        // buffer overflow fallback (P ~ 1e-9 per thread): ids via exact rescan
        #pragma unroll 1
        for (int j = 0; j < N_ && w < KNN; j++) {
            float4 c = sh[j];
            float d = fmaf(c.x, m2x, fmaf(c.y, m2y, fmaf(c.z, m2z, c.w)));
            if (d <= thresh) ids[w++] = (unsigned)j;
        }
    }
    while (w < KNN) ids[w++] = ids[0];   // safety (unreachable)

    // ---- exact d0 + inside votes ----
    float D = q.w + a[0];
    float d0 = sqrtf(fmaxf(D, 0.f));

    int votes = 0;
    const float4* nrm = g_nrm4 + o * N_;
    #pragma unroll
    for (int s = 0; s < KNN; s++) {
        unsigned id = ids[s];
        float4 c  = sh[id];
        float4 nm = __ldg(&nrm[id]);
        float dt = (c.x - q.x) * nm.x + (c.y - q.y) * nm.y + (c.z - q.z) * nm.z;
        votes += (dt > 0.f) ? 1 : 0;
    }
    float sd = (votes > 8) ? -d0 : d0;   // sum(insides) > 0.8*k -> >= 9
    g_scr[b][oi][n] = sd;
}

// ---------------- kernel 3: min over other objects + plane, write out ----------------
__global__ void finalize_kernel(float* __restrict__ out, int out_size) {
    int i = blockIdx.x * blockDim.x + threadIdx.x;
    if (i >= O_ * N_) return;
    int b = i / N_;
    int n = i % N_;
    float sd = g_pip4[i].z;                 // plane signed distance = pip.z
    sd = fminf(sd, g_scr[b][0][n]);
    sd = fminf(sd, g_scr[b][1][n]);
    sd = fminf(sd, g_scr[b][2][n]);
    out[i] = sd;
    if (out_size >= 2 * O_ * N_)
        out[O_ * N_ + i] = (sd < -TOLC) ? 1.0f : 0.0f;
}

// ---------------- launch ----------------
extern "C" void kernel_launch(void* const* d_in, const int* in_sizes, int n_in,
                              void* d_out, int out_size) {
    const float* points  = nullptr;
    const float* T_obj   = nullptr;
    const float* T_plane = nullptr;
    for (int i = 0; i < n_in; i++) {
        if (in_sizes[i] == O_ * N_ * 6) points  = (const float*)d_in[i];
        else if (in_sizes[i] == 64)     T_obj   = (const float*)d_in[i];
        else if (in_sizes[i] == 16)     T_plane = (const float*)d_in[i];
    }

    transform_kernel<<<(O_ * N_ + 255) / 256, 256>>>(points, T_obj, T_plane);

    int smem = N_ * (int)sizeof(float4) + CAP * BTHR * (int)sizeof(unsigned short);
    (void)cudaFuncSetAttribute(knn_kernel,
                               cudaFuncAttributeMaxDynamicSharedMemorySize, smem);
    knn_kernel<<<dim3(N_ / BTHR, O_ * 3), BTHR, smem>>>();

    finalize_kernel<<<(O_ * N_ + 255) / 256, 256>>>((float*)d_out, out_size);
}